// round 1
// baseline (speedup 1.0000x reference)
#include <cuda_runtime.h>

#define NN 100000
#define NE 1000000
#define CH 128
#define BN_EPS 1e-5f

// ---------------- scratch (device globals: allowed, no runtime alloc) ----------------
__device__ __align__(16) float g_bufA[NN * CH];   // h (GEMM output)
__device__ __align__(16) float g_bufB[NN * CH];   // agg1 / y1
__device__ __align__(16) float g_dinv[NN];
__device__ __align__(16) float g_deg[NN];
__device__ __align__(16) float g_sum[CH];
__device__ __align__(16) float g_sumsq[CH];
__device__ __align__(16) float g_scale[CH];
__device__ __align__(16) float g_shift[CH];
__device__ __align__(16) float g_Wt[CH * CH];     // folded W, transposed: Wt[c][j]
__device__ __align__(16) float g_bb[CH];          // folded bias (pre-aggregation)

// ---------------- degree ----------------
__global__ void k_zero_deg_sums() {
    int i = blockIdx.x * blockDim.x + threadIdx.x;
    if (i < NN) g_deg[i] = 0.0f;
    if (i < CH) { g_sum[i] = 0.0f; g_sumsq[i] = 0.0f; }
}

__global__ void k_zero_sums() {
    int c = threadIdx.x;
    g_sum[c] = 0.0f; g_sumsq[c] = 0.0f;
}

__global__ void k_count_deg(const int* __restrict__ dst) {
    int e = blockIdx.x * blockDim.x + threadIdx.x;
    if (e < NE) atomicAdd(&g_deg[dst[e]], 1.0f);
}

__global__ void k_finish_deg() {
    int i = blockIdx.x * blockDim.x + threadIdx.x;
    if (i < NN) g_dinv[i] = rsqrtf(g_deg[i] + 1.0f);  // +1 self loop; deg >= 1 always
}

// ---------------- BN stats ----------------
__global__ void k_bn_stats(const float* __restrict__ X) {
    __shared__ float sh[256];
    int c = threadIdx.x & 127;
    int rloc = threadIdx.x >> 7;                 // 0 or 1
    float s = 0.0f, ss = 0.0f;
    for (int r = blockIdx.x * 2 + rloc; r < NN; r += gridDim.x * 2) {
        float v = X[(size_t)r * CH + c];
        s += v; ss += v * v;
    }
    sh[threadIdx.x] = s;
    __syncthreads();
    if (threadIdx.x < 128) atomicAdd(&g_sum[c], sh[threadIdx.x] + sh[threadIdx.x + 128]);
    __syncthreads();
    sh[threadIdx.x] = ss;
    __syncthreads();
    if (threadIdx.x < 128) atomicAdd(&g_sumsq[c], sh[threadIdx.x] + sh[threadIdx.x + 128]);
}

__global__ void k_bn_finalize(const float* __restrict__ gamma, const float* __restrict__ beta) {
    int c = threadIdx.x;
    float inv_n = 1.0f / (float)NN;
    float mean = g_sum[c] * inv_n;
    float var = g_sumsq[c] * inv_n - mean * mean;
    if (var < 0.0f) var = 0.0f;
    float s = gamma[c] * rsqrtf(var + BN_EPS);
    g_scale[c] = s;
    g_shift[c] = beta[c] - mean * s;
}

// ---------------- fold BN into weights ----------------
// Wt[c][j] = W[j][c] * scale[c]; bb[j] = sum_c shift[c]*W[j][c]
__global__ void k_fold_w(const float* __restrict__ W) {
    __shared__ float red[128];
    int j = blockIdx.x;
    int c = threadIdx.x;
    float w = W[j * CH + c];
    g_Wt[c * CH + j] = w * g_scale[c];
    red[c] = w * g_shift[c];
    __syncthreads();
    for (int off = 64; off > 0; off >>= 1) {
        if (c < off) red[c] += red[c + off];
        __syncthreads();
    }
    if (c == 0) g_bb[j] = red[0];
}

// ---------------- GEMM: C[N,128] = A[N,128] @ Wt + bb ----------------
// Block: 256 threads, 64 rows x 128 cols tile. Each thread: 8 rows x 4 cols.
#define GEMM_TM 64
__global__ void k_gemm(const float* __restrict__ A, float* __restrict__ C, int nrows) {
    extern __shared__ float smem[];
    float* sW = smem;                 // [128][128]  64 KB
    float* sX = smem + CH * CH;       // [64][128]   32 KB
    const int tid = threadIdx.x;
    const int tx = tid & 31;          // col quad: cols tx*4 .. tx*4+3
    const int ty = tid >> 5;          // row group: rows ty*8 .. ty*8+7
    const int row0 = blockIdx.x * GEMM_TM;

    // load folded weights into shared (4096 float4 / 256 threads = 16 each)
    const float4* Wt4 = (const float4*)g_Wt;
    float4* sW4 = (float4*)sW;
#pragma unroll
    for (int i = 0; i < 16; i++) sW4[tid + i * 256] = Wt4[tid + i * 256];

    // load X tile (2048 float4 / 256 threads = 8 each)
    const float4* A4 = (const float4*)A;
    float4* sX4 = (float4*)sX;
#pragma unroll
    for (int i = 0; i < 8; i++) {
        int idx = tid + i * 256;
        int rr = idx >> 5, cc = idx & 31;
        int gr = row0 + rr;
        float4 v = (gr < nrows) ? A4[(size_t)gr * 32 + cc] : make_float4(0.f, 0.f, 0.f, 0.f);
        sX4[idx] = v;
    }
    __syncthreads();

    float acc[8][4];
#pragma unroll
    for (int i = 0; i < 8; i++) { acc[i][0] = 0.f; acc[i][1] = 0.f; acc[i][2] = 0.f; acc[i][3] = 0.f; }

    const float* xrow = &sX[(ty * 8) * CH];
#pragma unroll 4
    for (int k = 0; k < CH; k++) {
        float4 wv = *(const float4*)(&sW[k * CH + (tx << 2)]);
#pragma unroll
        for (int i = 0; i < 8; i++) {
            float xv = xrow[i * CH + k];
            acc[i][0] = fmaf(xv, wv.x, acc[i][0]);
            acc[i][1] = fmaf(xv, wv.y, acc[i][1]);
            acc[i][2] = fmaf(xv, wv.z, acc[i][2]);
            acc[i][3] = fmaf(xv, wv.w, acc[i][3]);
        }
    }

    float4 bb = *(const float4*)&g_bb[tx << 2];
    float4* C4 = (float4*)C;
#pragma unroll
    for (int i = 0; i < 8; i++) {
        int r = row0 + ty * 8 + i;
        if (r < nrows) {
            float4 o;
            o.x = acc[i][0] + bb.x; o.y = acc[i][1] + bb.y;
            o.z = acc[i][2] + bb.z; o.w = acc[i][3] + bb.w;
            C4[(size_t)r * 32 + tx] = o;
        }
    }
}

// ---------------- aggregation ----------------
// OUT[i] = H[i] * dinv[i]^2  (self loop term, also initializes OUT)
__global__ void k_selfloop_init(const float* __restrict__ H, float* __restrict__ OUT) {
    int idx = blockIdx.x * blockDim.x + threadIdx.x;   // over N*32 float4s
    if (idx >= NN * 32) return;
    int r = idx >> 5;
    float di = g_dinv[r];
    float sc = di * di;
    float4 v = ((const float4*)H)[idx];
    v.x *= sc; v.y *= sc; v.z *= sc; v.w *= sc;
    ((float4*)OUT)[idx] = v;
}

// one warp per edge; lane handles one float4 (32*4 = 128 channels)
__global__ void k_edge_scatter(const float* __restrict__ H, float* __restrict__ OUT,
                               const int* __restrict__ src, const int* __restrict__ dst) {
    int e = (blockIdx.x * blockDim.x + threadIdx.x) >> 5;
    int lane = threadIdx.x & 31;
    if (e >= NE) return;
    int s = __ldg(&src[e]);
    int d = __ldg(&dst[e]);
    float nrm = g_dinv[s] * g_dinv[d];
    float4 v = *(const float4*)&H[(size_t)s * CH + (lane << 2)];
    v.x *= nrm; v.y *= nrm; v.z *= nrm; v.w *= nrm;
    const float* p = &OUT[(size_t)d * CH + (lane << 2)];
    asm volatile("red.global.add.v4.f32 [%0], {%1,%2,%3,%4};"
                 :: "l"(p), "f"(v.x), "f"(v.y), "f"(v.z), "f"(v.w) : "memory");
}

// Y = relu(Y + b) in place
__global__ void k_relu_bias(float* __restrict__ Y, const float* __restrict__ b) {
    int idx = blockIdx.x * blockDim.x + threadIdx.x;
    if (idx >= NN * 32) return;
    int c4 = idx & 31;
    float4 bv = ((const float4*)b)[c4];
    float4 v = ((float4*)Y)[idx];
    v.x = fmaxf(v.x + bv.x, 0.f); v.y = fmaxf(v.y + bv.y, 0.f);
    v.z = fmaxf(v.z + bv.z, 0.f); v.w = fmaxf(v.w + bv.w, 0.f);
    ((float4*)Y)[idx] = v;
}

// OUT = relu(OUT + b) + X  in place
__global__ void k_final(float* __restrict__ OUT, const float* __restrict__ b,
                        const float* __restrict__ X) {
    int idx = blockIdx.x * blockDim.x + threadIdx.x;
    if (idx >= NN * 32) return;
    int c4 = idx & 31;
    float4 bv = ((const float4*)b)[c4];
    float4 v = ((float4*)OUT)[idx];
    float4 xv = ((const float4*)X)[idx];
    v.x = fmaxf(v.x + bv.x, 0.f) + xv.x;
    v.y = fmaxf(v.y + bv.y, 0.f) + xv.y;
    v.z = fmaxf(v.z + bv.z, 0.f) + xv.z;
    v.w = fmaxf(v.w + bv.w, 0.f) + xv.w;
    ((float4*)OUT)[idx] = v;
}

// ---------------- launch ----------------
extern "C" void kernel_launch(void* const* d_in, const int* in_sizes, int n_in,
                              void* d_out, int out_size) {
    const float* x      = (const float*)d_in[0];
    const int*   ei     = (const int*)d_in[1];
    const float* W1     = (const float*)d_in[2];
    const float* b1     = (const float*)d_in[3];
    const float* W2     = (const float*)d_in[4];
    const float* b2     = (const float*)d_in[5];
    const float* gamma1 = (const float*)d_in[6];
    const float* beta1  = (const float*)d_in[7];
    const float* gamma2 = (const float*)d_in[8];
    const float* beta2  = (const float*)d_in[9];
    float* out = (float*)d_out;
    const int* src = ei;
    const int* dst = ei + NE;

    static bool attr_set = false;
    if (!attr_set) {
        cudaFuncSetAttribute(k_gemm, cudaFuncAttributeMaxDynamicSharedMemorySize, 98304);
        attr_set = true;
    }

    const int T = 256;
    int blkN    = (NN + T - 1) / T;          // node-count grids
    int blkE    = (NE + T - 1) / T;          // edge-count grids
    int blkElem = (NN * 32 + T - 1) / T;     // float4 elementwise grids
    int blkScat = (NE * 32 + T - 1) / T;     // warp-per-edge grids
    int blkGemm = (NN + GEMM_TM - 1) / GEMM_TM;

    // degree / norm
    k_zero_deg_sums<<<blkN, T>>>();
    k_count_deg<<<blkE, T>>>(dst);
    k_finish_deg<<<blkN, T>>>();

    // ---- layer 1: BN1 folded into GEMM1 ----
    k_bn_stats<<<256, T>>>(x);
    k_bn_finalize<<<1, 128>>>(gamma1, beta1);
    k_fold_w<<<128, 128>>>(W1);
    k_gemm<<<blkGemm, T, 98304>>>(x, g_bufA, NN);
    k_selfloop_init<<<blkElem, T>>>(g_bufA, g_bufB);
    k_edge_scatter<<<blkScat, T>>>(g_bufA, g_bufB, src, dst);
    k_relu_bias<<<blkElem, T>>>(g_bufB, b1);

    // ---- layer 2 ----
    k_zero_sums<<<1, 128>>>();
    k_bn_stats<<<256, T>>>(g_bufB);
    k_bn_finalize<<<1, 128>>>(gamma2, beta2);
    k_fold_w<<<128, 128>>>(W2);
    k_gemm<<<blkGemm, T, 98304>>>(g_bufB, g_bufA, NN);
    k_selfloop_init<<<blkElem, T>>>(g_bufA, out);
    k_edge_scatter<<<blkScat, T>>>(g_bufA, out, src, dst);
    k_final<<<blkElem, T>>>(out, b2, x);
}

// round 2
// speedup vs baseline: 1.4872x; 1.4872x over previous
#include <cuda_runtime.h>

#define NN 100000
#define NE 1000000
#define CH 128
#define BN_EPS 1e-5f

#define SCAN_CHUNK 512
#define NCHUNK ((NN + SCAN_CHUNK - 1) / SCAN_CHUNK)   // 196

// ---------------- scratch (device globals) ----------------
__device__ __align__(16) float g_bufA[NN * CH];   // h (GEMM output)
__device__ __align__(16) float g_bufB[NN * CH];   // y1
__device__ __align__(16) float g_dinv[NN];
__device__ int   g_cnt[NN];
__device__ int   g_fill[NN];
__device__ int   g_off[NN + 1];
__device__ int   g_offtmp[NN];
__device__ int   g_bsum[NCHUNK];
__device__ int   g_bsum2[NCHUNK];
__device__ int   g_eidx[NE];                      // src ids sorted by dst
__device__ __align__(16) float g_sum[CH];
__device__ __align__(16) float g_sumsq[CH];
__device__ __align__(16) float g_scale[CH];
__device__ __align__(16) float g_shift[CH];
__device__ __align__(16) float g_Wt[CH * CH];     // folded W^T
__device__ __align__(16) float g_bb[CH];          // folded BN-shift bias

// ---------------- init / degree / CSR ----------------
__global__ void k_zero() {
    int i = blockIdx.x * blockDim.x + threadIdx.x;
    if (i < NN) { g_cnt[i] = 0; g_fill[i] = 0; }
    if (i < CH) { g_sum[i] = 0.0f; g_sumsq[i] = 0.0f; }
}

__global__ void k_zero_sums() {
    int c = threadIdx.x;
    g_sum[c] = 0.0f; g_sumsq[c] = 0.0f;
}

__global__ void k_hist(const int* __restrict__ dst) {
    int e = blockIdx.x * blockDim.x + threadIdx.x;
    if (e < NE) atomicAdd(&g_cnt[dst[e]], 1);
}

__global__ void k_dinv() {
    int i = blockIdx.x * blockDim.x + threadIdx.x;
    if (i < NN) g_dinv[i] = rsqrtf((float)g_cnt[i] + 1.0f);  // +1 self loop
}

__global__ void k_scan1() {
    __shared__ int sh[SCAN_CHUNK];
    int t = threadIdx.x;
    int gid = blockIdx.x * SCAN_CHUNK + t;
    int v = (gid < NN) ? g_cnt[gid] : 0;
    sh[t] = v;
    __syncthreads();
    for (int off = 1; off < SCAN_CHUNK; off <<= 1) {
        int add = (t >= off) ? sh[t - off] : 0;
        __syncthreads();
        sh[t] += add;
        __syncthreads();
    }
    if (gid < NN) g_offtmp[gid] = sh[t];
    if (t == SCAN_CHUNK - 1) g_bsum[blockIdx.x] = sh[t];
}

__global__ void k_scan2() {
    __shared__ int sh[256];
    int t = threadIdx.x;
    int v = (t < NCHUNK) ? g_bsum[t] : 0;
    sh[t] = v;
    __syncthreads();
    for (int off = 1; off < 256; off <<= 1) {
        int add = (t >= off) ? sh[t - off] : 0;
        __syncthreads();
        sh[t] += add;
        __syncthreads();
    }
    if (t < NCHUNK) g_bsum2[t] = sh[t];
}

__global__ void k_scan3() {
    int t = threadIdx.x;
    int gid = blockIdx.x * SCAN_CHUNK + t;
    int base = (blockIdx.x > 0) ? g_bsum2[blockIdx.x - 1] : 0;
    if (gid < NN) g_off[gid + 1] = g_offtmp[gid] + base;
    if (gid == 0) g_off[0] = 0;
}

__global__ void k_fill(const int* __restrict__ src, const int* __restrict__ dst) {
    int e = blockIdx.x * blockDim.x + threadIdx.x;
    if (e >= NE) return;
    int d = dst[e];
    int pos = g_off[d] + atomicAdd(&g_fill[d], 1);
    g_eidx[pos] = src[e];
}

// ---------------- BN stats (float4, 8 rows/block/iter) ----------------
__global__ void k_bn_stats(const float* __restrict__ X) {
    __shared__ float4 shs[256];
    __shared__ float4 shss[256];
    int lane = threadIdx.x & 31;     // float4 column
    int r = threadIdx.x >> 5;        // 0..7
    float4 s = make_float4(0.f, 0.f, 0.f, 0.f);
    float4 ss = make_float4(0.f, 0.f, 0.f, 0.f);
    const float4* X4 = (const float4*)X;
    for (int row = blockIdx.x * 8 + r; row < NN; row += gridDim.x * 8) {
        float4 v = X4[(size_t)row * 32 + lane];
        s.x += v.x; s.y += v.y; s.z += v.z; s.w += v.w;
        ss.x += v.x * v.x; ss.y += v.y * v.y; ss.z += v.z * v.z; ss.w += v.w * v.w;
    }
    shs[threadIdx.x] = s; shss[threadIdx.x] = ss;
    __syncthreads();
    if (r == 0) {
#pragma unroll
        for (int w = 1; w < 8; w++) {
            float4 a = shs[w * 32 + lane];
            float4 b = shss[w * 32 + lane];
            s.x += a.x; s.y += a.y; s.z += a.z; s.w += a.w;
            ss.x += b.x; ss.y += b.y; ss.z += b.z; ss.w += b.w;
        }
        const float* ps = &g_sum[lane << 2];
        const float* pq = &g_sumsq[lane << 2];
        asm volatile("red.global.add.v4.f32 [%0], {%1,%2,%3,%4};"
                     :: "l"(ps), "f"(s.x), "f"(s.y), "f"(s.z), "f"(s.w) : "memory");
        asm volatile("red.global.add.v4.f32 [%0], {%1,%2,%3,%4};"
                     :: "l"(pq), "f"(ss.x), "f"(ss.y), "f"(ss.z), "f"(ss.w) : "memory");
    }
}

__global__ void k_bn_finalize(const float* __restrict__ gamma, const float* __restrict__ beta) {
    int c = threadIdx.x;
    float inv_n = 1.0f / (float)NN;
    float mean = g_sum[c] * inv_n;
    float var = g_sumsq[c] * inv_n - mean * mean;
    if (var < 0.0f) var = 0.0f;
    float s = gamma[c] * rsqrtf(var + BN_EPS);
    g_scale[c] = s;
    g_shift[c] = beta[c] - mean * s;
}

// ---------------- fold BN into weights ----------------
__global__ void k_fold_w(const float* __restrict__ W) {
    __shared__ float red[128];
    int j = blockIdx.x;
    int c = threadIdx.x;
    float w = W[j * CH + c];
    g_Wt[c * CH + j] = w * g_scale[c];
    red[c] = w * g_shift[c];
    __syncthreads();
    for (int off = 64; off > 0; off >>= 1) {
        if (c < off) red[c] += red[c + off];
        __syncthreads();
    }
    if (c == 0) g_bb[j] = red[0];
}

// ---------------- GEMM: C = A @ Wt + bb ----------------
#define GEMM_TM 64
__global__ void __launch_bounds__(256) k_gemm(const float* __restrict__ A, float* __restrict__ C, int nrows) {
    extern __shared__ float smem[];
    float* sW = smem;                 // [128][128]
    float* sX = smem + CH * CH;       // [64][128]
    const int tid = threadIdx.x;
    const int tx = tid & 31;
    const int ty = tid >> 5;
    const int row0 = blockIdx.x * GEMM_TM;

    const float4* Wt4 = (const float4*)g_Wt;
    float4* sW4 = (float4*)sW;
#pragma unroll
    for (int i = 0; i < 16; i++) sW4[tid + i * 256] = Wt4[tid + i * 256];

    const float4* A4 = (const float4*)A;
    float4* sX4 = (float4*)sX;
#pragma unroll
    for (int i = 0; i < 8; i++) {
        int idx = tid + i * 256;
        int rr = idx >> 5, cc = idx & 31;
        int gr = row0 + rr;
        float4 v = (gr < nrows) ? A4[(size_t)gr * 32 + cc] : make_float4(0.f, 0.f, 0.f, 0.f);
        sX4[idx] = v;
    }
    __syncthreads();

    float acc[8][4];
#pragma unroll
    for (int i = 0; i < 8; i++) { acc[i][0] = 0.f; acc[i][1] = 0.f; acc[i][2] = 0.f; acc[i][3] = 0.f; }

    const float* xrow = &sX[(ty * 8) * CH];
#pragma unroll 4
    for (int k = 0; k < CH; k++) {
        float4 wv = *(const float4*)(&sW[k * CH + (tx << 2)]);
#pragma unroll
        for (int i = 0; i < 8; i++) {
            float xv = xrow[i * CH + k];
            acc[i][0] = fmaf(xv, wv.x, acc[i][0]);
            acc[i][1] = fmaf(xv, wv.y, acc[i][1]);
            acc[i][2] = fmaf(xv, wv.z, acc[i][2]);
            acc[i][3] = fmaf(xv, wv.w, acc[i][3]);
        }
    }

    float4 bb = *(const float4*)&g_bb[tx << 2];
    float4* C4 = (float4*)C;
#pragma unroll
    for (int i = 0; i < 8; i++) {
        int r = row0 + ty * 8 + i;
        if (r < nrows) {
            float4 o;
            o.x = acc[i][0] + bb.x; o.y = acc[i][1] + bb.y;
            o.z = acc[i][2] + bb.z; o.w = acc[i][3] + bb.w;
            C4[(size_t)r * 32 + tx] = o;
        }
    }
}

// ---------------- gather aggregation (warp per dst node) ----------------
// OUT[d] = relu( sum_{s in N(d)} H[s]*dinv[s]*dinv[d] + H[d]*dinv[d]^2 + bias ) [+ xres]
__global__ void k_gather(const float* __restrict__ H, float* __restrict__ OUT,
                         const float* __restrict__ bias, const float* __restrict__ xres,
                         int add_res) {
    int warp = (blockIdx.x * blockDim.x + threadIdx.x) >> 5;
    int lane = threadIdx.x & 31;
    if (warp >= NN) return;
    int d = warp;
    float dd = g_dinv[d];
    const float4* H4 = (const float4*)H;

    float4 h = H4[(size_t)d * 32 + lane];
    float sc = dd * dd;
    float4 acc = make_float4(h.x * sc, h.y * sc, h.z * sc, h.w * sc);

    int j = g_off[d];
    int end = g_off[d + 1];
    // 2x unrolled gather for MLP
    for (; j + 1 < end; j += 2) {
        int s0 = g_eidx[j];
        int s1 = g_eidx[j + 1];
        float n0 = g_dinv[s0] * dd;
        float n1 = g_dinv[s1] * dd;
        float4 v0 = H4[(size_t)s0 * 32 + lane];
        float4 v1 = H4[(size_t)s1 * 32 + lane];
        acc.x = fmaf(v0.x, n0, acc.x); acc.y = fmaf(v0.y, n0, acc.y);
        acc.z = fmaf(v0.z, n0, acc.z); acc.w = fmaf(v0.w, n0, acc.w);
        acc.x = fmaf(v1.x, n1, acc.x); acc.y = fmaf(v1.y, n1, acc.y);
        acc.z = fmaf(v1.z, n1, acc.z); acc.w = fmaf(v1.w, n1, acc.w);
    }
    if (j < end) {
        int s0 = g_eidx[j];
        float n0 = g_dinv[s0] * dd;
        float4 v0 = H4[(size_t)s0 * 32 + lane];
        acc.x = fmaf(v0.x, n0, acc.x); acc.y = fmaf(v0.y, n0, acc.y);
        acc.z = fmaf(v0.z, n0, acc.z); acc.w = fmaf(v0.w, n0, acc.w);
    }

    float4 bv = ((const float4*)bias)[lane];
    acc.x = fmaxf(acc.x + bv.x, 0.f); acc.y = fmaxf(acc.y + bv.y, 0.f);
    acc.z = fmaxf(acc.z + bv.z, 0.f); acc.w = fmaxf(acc.w + bv.w, 0.f);
    if (add_res) {
        float4 xv = ((const float4*)xres)[(size_t)d * 32 + lane];
        acc.x += xv.x; acc.y += xv.y; acc.z += xv.z; acc.w += xv.w;
    }
    ((float4*)OUT)[(size_t)d * 32 + lane] = acc;
}

// ---------------- launch ----------------
extern "C" void kernel_launch(void* const* d_in, const int* in_sizes, int n_in,
                              void* d_out, int out_size) {
    const float* x      = (const float*)d_in[0];
    const int*   ei     = (const int*)d_in[1];
    const float* W1     = (const float*)d_in[2];
    const float* b1     = (const float*)d_in[3];
    const float* W2     = (const float*)d_in[4];
    const float* b2     = (const float*)d_in[5];
    const float* gamma1 = (const float*)d_in[6];
    const float* beta1  = (const float*)d_in[7];
    const float* gamma2 = (const float*)d_in[8];
    const float* beta2  = (const float*)d_in[9];
    float* out = (float*)d_out;
    const int* src = ei;
    const int* dst = ei + NE;

    static bool attr_set = false;
    if (!attr_set) {
        cudaFuncSetAttribute(k_gemm, cudaFuncAttributeMaxDynamicSharedMemorySize, 98304);
        attr_set = true;
    }

    const int T = 256;
    int blkN    = (NN + T - 1) / T;
    int blkE    = (NE + T - 1) / T;
    int blkGemm = (NN + GEMM_TM - 1) / GEMM_TM;
    int blkGath = (NN * 32 + T - 1) / T;      // warp per node

    // CSR build (once, shared by both convs)
    k_zero<<<blkN, T>>>();
    k_hist<<<blkE, T>>>(dst);
    k_dinv<<<blkN, T>>>();
    k_scan1<<<NCHUNK, SCAN_CHUNK>>>();
    k_scan2<<<1, 256>>>();
    k_scan3<<<NCHUNK, SCAN_CHUNK>>>();
    k_fill<<<blkE, T>>>(src, dst);

    // ---- layer 1 ----
    k_bn_stats<<<592, T>>>(x);
    k_bn_finalize<<<1, 128>>>(gamma1, beta1);
    k_fold_w<<<128, 128>>>(W1);
    k_gemm<<<blkGemm, T, 98304>>>(x, g_bufA, NN);
    k_gather<<<blkGath, T>>>(g_bufA, g_bufB, b1, nullptr, 0);

    // ---- layer 2 ----
    k_zero_sums<<<1, 128>>>();
    k_bn_stats<<<592, T>>>(g_bufB);
    k_bn_finalize<<<1, 128>>>(gamma2, beta2);
    k_fold_w<<<128, 128>>>(W2);
    k_gemm<<<blkGemm, T, 98304>>>(g_bufB, g_bufA, NN);
    k_gather<<<blkGath, T>>>(g_bufA, out, b2, x, 1);
}